// round 15
// baseline (speedup 1.0000x reference)
#include <cuda_runtime.h>
#include <cuda_bf16.h>
#include <math.h>

#define SEQ 17520
#define NB 16
#define NCH 64
#define CHUNK 48
#define NCHK 365   // 365*48 = 17520 exactly

typedef unsigned long long u64;
typedef unsigned u32;

// ---------------- device scratch (no allocation allowed) ----------------
__device__ float4 g_pre4[SEQ * NCH];            // [t_exec][chain] gate affines
__device__ float  g_hraw[SEQ * NCH];            // [t_exec][chain] raw hidden states
__device__ float  g_hTm[32 * SEQ];              // encoder output [m][t]
__device__ float  g_bufAm[32 * 13140];          // activations [m][K]
__device__ float  g_bufBm[32 * 8760];
__device__ float  g_zi2[32 * 1752];
__device__ float  g_zc4[10 * 32];
__device__ float  g_part[3200000];              // split-K partials [split][tile][n(128)][m(32)]

// ---------------- helpers ----------------
__device__ __forceinline__ float tanhf_a(float x) {
    float y; asm("tanh.approx.f32 %0, %1;" : "=f"(y) : "f"(x)); return y;
}
__device__ __forceinline__ float4 ldg4z(const float* p, int k, int kmax) {
    float4 v = make_float4(0.f, 0.f, 0.f, 0.f);
    if (k + 3 < kmax) { v = *(const float4*)p; }
    else {
        if (k     < kmax) v.x = p[0];
        if (k + 1 < kmax) v.y = p[1];
        if (k + 2 < kmax) v.z = p[2];
        if (k + 3 < kmax) v.w = p[3];
    }
    return v;
}
// fp32x4 -> bf16 hi pairs + lo(residual) pairs
__device__ __forceinline__ void cvt4(float4 f, u32& hi0, u32& hi1, u32& lo0, u32& lo1) {
    __nv_bfloat162 h01 = __floats2bfloat162_rn(f.x, f.y);
    __nv_bfloat162 h23 = __floats2bfloat162_rn(f.z, f.w);
    hi0 = *(u32*)&h01; hi1 = *(u32*)&h23;
    float r0 = f.x - __low2float(h01), r1 = f.y - __high2float(h01);
    float r2 = f.z - __low2float(h23), r3 = f.w - __high2float(h23);
    __nv_bfloat162 l01 = __floats2bfloat162_rn(r0, r1);
    __nv_bfloat162 l23 = __floats2bfloat162_rn(r2, r3);
    lo0 = *(u32*)&l01; lo1 = *(u32*)&l23;
}
__device__ __forceinline__ void mma16816(float* c, u32 a0, u32 a1, u32 a2, u32 a3,
                                         u32 b0, u32 b1) {
    asm volatile("mma.sync.aligned.m16n8k16.row.col.f32.bf16.bf16.f32 "
        "{%0,%1,%2,%3}, {%4,%5,%6,%7}, {%8,%9}, {%0,%1,%2,%3};"
        : "+f"(c[0]), "+f"(c[1]), "+f"(c[2]), "+f"(c[3])
        : "r"(a0), "r"(a1), "r"(a2), "r"(a3), "r"(b0), "r"(b1));
}

// ---------------- 1. gate-affine precompute ----------------
__global__ void pre_kernel(const float* __restrict__ x_t, const float* __restrict__ x_aug,
                           const float* __restrict__ Wih_f, const float* __restrict__ b_f,
                           const float* __restrict__ Wih_b, const float* __restrict__ b_b) {
    int idx = blockIdx.x * 256 + threadIdx.x;
    int c = idx & 63, t = idx >> 6;
    int in = c >> 5, dir = (c >> 4) & 1, b = c & 15;
    const float* x   = in  ? x_aug : x_t;
    const float* Wih = dir ? Wih_b : Wih_f;
    const float* bb  = dir ? b_b   : b_f;
    float xv = x[b * SEQ + (dir ? (SEQ - 1 - t) : t)];
    float4 o;
    o.x = 0.5f * fmaf(xv, Wih[0], bb[0]);
    o.y = 0.5f * fmaf(xv, Wih[1], bb[1]);
    o.z =        fmaf(xv, Wih[2], bb[2]);
    o.w = 0.5f * fmaf(xv, Wih[3], bb[3]);
    g_pre4[t * NCH + c] = o;
}

// ---------------- 2. LSTM recurrence (R5 exact) ----------------
extern __shared__ char dynsmem[];

__device__ __forceinline__ void lstm_step(float4 p, float& h, float& C,
                                          float wi2, float wf2, float wg, float wo2) {
    float ti = tanhf_a(fmaf(h, wi2, p.x));
    float tf = tanhf_a(fmaf(h, wf2, p.y));
    float tg = tanhf_a(fmaf(h, wg,  p.z));
    float to = tanhf_a(fmaf(h, wo2, p.w));
    float i = fmaf(ti, 0.5f, 0.5f);
    float f = fmaf(tf, 0.5f, 0.5f);
    float o = fmaf(to, 0.5f, 0.5f);
    C = fmaf(f, C, i * tg);
    h = o * tanhf_a(C);
}

__global__ void __launch_bounds__(256, 1)
lstm_kernel(const float* __restrict__ Whh_f, const float* __restrict__ Whh_b) {
    float4* sbuf = (float4*)dynsmem;
    float*  sh   = (float*)(dynsmem + 2 * CHUNK * 64 * 16);
    int tid = threadIdx.x;

    if (tid >= 64) {
        int pt = tid - 64;
        const float4* src = (const float4*)g_pre4;
        for (int i = pt; i < CHUNK * 64; i += 192) sbuf[i] = src[i];
    }
    __syncthreads();

    if (tid < 64) {
        int c = tid;
        int dir = (c >> 4) & 1;
        const float* Whh = dir ? Whh_b : Whh_f;
        float wi2 = 0.5f * Whh[0], wf2 = 0.5f * Whh[1];
        float wg  =        Whh[2], wo2 = 0.5f * Whh[3];
        float h = 0.0f, C = 0.0f;
        for (int ch = 0; ch < NCHK; ++ch) {
            int cur = ch & 1;
            const float4* buf = sbuf + cur * CHUNK * 64;
            float* hdst = sh + cur * CHUNK * 64;
            float4 p = buf[c];
#pragma unroll 4
            for (int s = 0; s < CHUNK; ++s) {
                float4 pn = buf[(s + 1) * 64 + c];
                lstm_step(p, h, C, wi2, wf2, wg, wo2);
                hdst[s * 64 + c] = h;
                p = pn;
            }
            __syncthreads();
        }
    } else {
        int pt = tid - 64;
        const float4* src = (const float4*)g_pre4;
        for (int ch = 0; ch < NCHK; ++ch) {
            int cur = ch & 1, nxt = cur ^ 1;
            if (ch + 1 < NCHK) {
                const float4* s4 = src + (size_t)(ch + 1) * CHUNK * 64;
                float4* d4 = sbuf + nxt * CHUNK * 64;
                for (int i = pt; i < CHUNK * 64; i += 192) d4[i] = s4[i];
            }
            if (ch >= 1) {
                const float* hs = sh + nxt * CHUNK * 64;
                float* gd = g_hraw + (size_t)(ch - 1) * CHUNK * 64;
                for (int i = pt; i < CHUNK * 64; i += 192) gd[i] = hs[i];
            }
            __syncthreads();
        }
        const float* hs = sh + ((NCHK - 1) & 1) * CHUNK * 64;
        float* gd = g_hraw + (size_t)(NCHK - 1) * CHUNK * 64;
        for (int i = pt; i < CHUNK * 64; i += 192) gd[i] = hs[i];
    }
}

// ---------------- 3. combine -> h_enc [m][t] ----------------
__global__ void combine_kernel(const float* __restrict__ Wl, const float* __restrict__ bl) {
    int idx = blockIdx.x * 256 + threadIdx.x;
    int t = idx >> 5, m = idx & 31;
    int in = m >> 4, b = m & 15;
    float hf = g_hraw[(size_t)t * 64 + in * 32 + b];
    float hb = g_hraw[(size_t)(SEQ - 1 - t) * 64 + in * 32 + 16 + b];
    g_hTm[(size_t)m * SEQ + t] = fmaf(Wl[0], hf, fmaf(Wl[1], hb, bl[0]));
}

// ---------------- 4. GEMM: mma.sync bf16 hi/lo split, split-K ----------------
// D tile 128n x 32m. Block of 64 k per iteration.
// W-frags stored in exact mma A-layout (lane-permuted, slot-class rotated),
// act-frags in exact mma B-layout. One LDS.128 / LDS.64 per fragment.
__global__ void __launch_bounds__(128, 3)
gemm_kernel(const float* __restrict__ A,   // activations [m=32][K]
            const float* __restrict__ W,   // [N][K]
            int N, int K) {
    __shared__ u32 sWh[8 * 4 * 32 * 4];   // [tn][tk][lane'][slot'] 16KB
    __shared__ u32 sWl[8 * 4 * 32 * 4];
    __shared__ u32 sAh[4 * 4 * 32 * 2];   // [tk][tm][lane][slot] 4KB
    __shared__ u32 sAl[4 * 4 * 32 * 2];

    int t = threadIdx.x, w = t >> 5, l = t & 31;
    int bt = blockIdx.x, bs = blockIdx.y;
    int ntiles = gridDim.x, nsp = gridDim.y;
    int n0 = bt * 128;
    int k0 = (int)(((long long)K * bs) / nsp) & ~63;
    int k1 = (bs == nsp - 1) ? K : ((int)(((long long)K * (bs + 1)) / nsp) & ~63);

    // writer ids (W): thread -> one of 128 rows
    int tnW = t >> 4, rW = t & 15, gW = rW & 7, srW = rW >> 3, tnpW = tnW & 1;
    int nW = n0 + t;
    // writer ids (acts): thread -> (m, k-tile)
    int mA = t >> 2, tkA = t & 3, mmA = mA & 7, tmA = mA >> 3;
    // reader ids
    int g = l >> 2, kp = l & 3;
    int lpr = g * 4 + ((kp + (g >> 1)) & 3);

    float acc[2][4][4];
#pragma unroll
    for (int i = 0; i < 2; ++i)
#pragma unroll
        for (int j = 0; j < 4; ++j)
#pragma unroll
            for (int q = 0; q < 4; ++q) acc[i][j][q] = 0.0f;

    uint4 wreg[16];   // (hi0,hi1,lo0,lo1) per k-quad
    uint4 areg[4];

    auto loadblk = [&](int kb) {
#pragma unroll
        for (int q = 0; q < 16; ++q) {
            int k = kb + q * 4;
            float4 v = make_float4(0.f, 0.f, 0.f, 0.f);
            if (nW < N && k < k1) v = ldg4z(W + (size_t)nW * K + k, k, k1);
            cvt4(v, wreg[q].x, wreg[q].y, wreg[q].z, wreg[q].w);
        }
#pragma unroll
        for (int q = 0; q < 4; ++q) {
            int k = kb + tkA * 16 + q * 4;
            float4 v = make_float4(0.f, 0.f, 0.f, 0.f);
            if (k < k1) v = ldg4z(A + (size_t)mA * K + k, k, k1);
            cvt4(v, areg[q].x, areg[q].y, areg[q].z, areg[q].w);
        }
    };

    auto stsblk = [&]() {
#pragma unroll
        for (int q = 0; q < 16; ++q) {
            int tk = q >> 2, kk4 = q & 3;
            int slk = kk4 >> 1, kp0 = (kk4 & 1) * 2;
            int slotp = ((srW + 2 * slk) + 2 * tnpW) & 3;
            int L0 = gW * 4 + ((kp0 + (gW >> 1)) & 3);
            int L1 = gW * 4 + ((kp0 + 1 + (gW >> 1)) & 3);
            int bidx = (tnW * 4 + tk) * 128;
            sWh[bidx + L0 * 4 + slotp] = wreg[q].x;
            sWh[bidx + L1 * 4 + slotp] = wreg[q].y;
            sWl[bidx + L0 * 4 + slotp] = wreg[q].z;
            sWl[bidx + L1 * 4 + slotp] = wreg[q].w;
        }
#pragma unroll
        for (int q = 0; q < 4; ++q) {
            int slk = q >> 1, kp0 = (q & 1) * 2;
            int bidx = (tkA * 4 + tmA) * 64;
            sAh[bidx + (mmA * 4 + kp0) * 2 + slk]     = areg[q].x;
            sAh[bidx + (mmA * 4 + kp0 + 1) * 2 + slk] = areg[q].y;
            sAl[bidx + (mmA * 4 + kp0) * 2 + slk]     = areg[q].z;
            sAl[bidx + (mmA * 4 + kp0 + 1) * 2 + slk] = areg[q].w;
        }
    };

    loadblk(k0);
    for (int kb = k0; kb < k1; kb += 64) {
        stsblk();
        __syncthreads();
        if (kb + 64 < k1) loadblk(kb + 64);
#pragma unroll
        for (int tk = 0; tk < 4; ++tk) {
            uint2 bh[4], bl_[4];
#pragma unroll
            for (int j = 0; j < 4; ++j) {
                bh[j]  = ((const uint2*)sAh)[(tk * 4 + j) * 32 + l];
                bl_[j] = ((const uint2*)sAl)[(tk * 4 + j) * 32 + l];
            }
#pragma unroll
            for (int i = 0; i < 2; ++i) {
                int tnl = 2 * w + i;
                uint4 qh = ((const uint4*)sWh)[(tnl * 4 + tk) * 32 + lpr];
                uint4 ql = ((const uint4*)sWl)[(tnl * 4 + tk) * 32 + lpr];
                u32 ah[4], al[4];
                if (tnl & 1) {
                    ah[0] = qh.z; ah[1] = qh.w; ah[2] = qh.x; ah[3] = qh.y;
                    al[0] = ql.z; al[1] = ql.w; al[2] = ql.x; al[3] = ql.y;
                } else {
                    ah[0] = qh.x; ah[1] = qh.y; ah[2] = qh.z; ah[3] = qh.w;
                    al[0] = ql.x; al[1] = ql.y; al[2] = ql.z; al[3] = ql.w;
                }
#pragma unroll
                for (int j = 0; j < 4; ++j) {
                    mma16816(acc[i][j], ah[0], ah[1], ah[2], ah[3], bh[j].x, bh[j].y);
                    mma16816(acc[i][j], al[0], al[1], al[2], al[3], bh[j].x, bh[j].y);
                    mma16816(acc[i][j], ah[0], ah[1], ah[2], ah[3], bl_[j].x, bl_[j].y);
                }
            }
        }
        __syncthreads();
    }

    // epilogue: partials [split][tile][n_loc(128)][m(32)]
    size_t base = (size_t)(bs * ntiles + bt) * 4096;
#pragma unroll
    for (int i = 0; i < 2; ++i) {
        int nl0 = (2 * w + i) * 16 + g;
#pragma unroll
        for (int j = 0; j < 4; ++j) {
            size_t idx = base + (size_t)nl0 * 32 + j * 8 + 2 * kp;
            *(float2*)&g_part[idx]           = make_float2(acc[i][j][0], acc[i][j][1]);
            *(float2*)&g_part[idx + 8 * 32]  = make_float2(acc[i][j][2], acc[i][j][3]);
        }
    }
}

// ---------------- 5. split-K reduce + bias -> out [m][N] ----------------
__global__ void reduce_kernel(const float* __restrict__ bias, float* __restrict__ out,
                              int N, int ntiles, int nsplit) {
    int q = blockIdx.x * 256 + threadIdx.x;
    if (q >= N * 8) return;
    int n = q >> 3, m4 = (q & 7) * 4;
    int bt = n >> 7, nl = n & 127;
    float b = bias[n];
    float4 s = make_float4(b, b, b, b);
    for (int sp = 0; sp < nsplit; ++sp) {
        const float4 v = *(const float4*)&g_part[((size_t)(sp * ntiles + bt) * 128 + nl) * 32 + m4];
        s.x += v.x; s.y += v.y; s.z += v.z; s.w += v.w;
    }
    out[(size_t)(m4 + 0) * N + n] = s.x;
    out[(size_t)(m4 + 1) * N + n] = s.y;
    out[(size_t)(m4 + 2) * N + n] = s.z;
    out[(size_t)(m4 + 3) * N + n] = s.w;
}

// ---------------- 6. tiny final cluster GEMM (10 x 4380) ----------------
__global__ void cluster4_kernel(const float* __restrict__ W, const float* __restrict__ bias) {
    __shared__ float red[8][32];
    int n = blockIdx.x, t = threadIdx.x;
    int m = t & 31, seg = t >> 5;
    float s = 0.0f;
    for (int k = seg; k < 4380; k += 8)
        s += g_bufAm[(size_t)m * 4380 + k] * W[n * 4380 + k];
    red[seg][m] = s;
    __syncthreads();
    if (seg == 0) {
        float tot = bias[n];
#pragma unroll
        for (int j = 0; j < 8; ++j) tot += red[j][m];
        g_zc4[n * 32 + m] = tot;
    }
}

// ---------------- 7. instance-head L2 normalize -> d_out ----------------
__global__ void norm_kernel(float* __restrict__ out) {
    __shared__ float red[256];
    int m = blockIdx.x;
    float ss = 0.0f;
    for (int f = threadIdx.x; f < 1752; f += 256) {
        float v = g_zi2[(size_t)m * 1752 + f]; ss += v * v;
    }
    red[threadIdx.x] = ss; __syncthreads();
    for (int s = 128; s > 0; s >>= 1) {
        if (threadIdx.x < s) red[threadIdx.x] += red[threadIdx.x + s];
        __syncthreads();
    }
    float inv = 1.0f / fmaxf(sqrtf(red[0]), 1e-12f);
    int in = m >> 4, b = m & 15;
    float* dst = out + in * (16 * 1752) + b * 1752;
    for (int f = threadIdx.x; f < 1752; f += 256)
        dst[f] = g_zi2[(size_t)m * 1752 + f] * inv;
}

// ---------------- 8. cluster-head softmax -> d_out ----------------
__global__ void softmax_kernel(float* __restrict__ out) {
    int m = threadIdx.x;
    float v[10]; float mx = -1e30f;
#pragma unroll
    for (int c = 0; c < 10; ++c) { v[c] = g_zc4[c * 32 + m]; mx = fmaxf(mx, v[c]); }
    float sum = 0.0f;
#pragma unroll
    for (int c = 0; c < 10; ++c) { v[c] = __expf(v[c] - mx); sum += v[c]; }
    float inv = 1.0f / sum;
    int in = m >> 4, b = m & 15;
    float* dst = out + 2 * 16 * 1752 + in * 160 + b * 10;
#pragma unroll
    for (int c = 0; c < 10; ++c) dst[c] = v[c] * inv;
}

// ---------------- launch ----------------
extern "C" void kernel_launch(void* const* d_in, const int* in_sizes, int n_in,
                              void* d_out, int out_size) {
    const float* x_t   = (const float*)d_in[0];
    const float* x_aug = (const float*)d_in[1];
    const float* Wih_f = (const float*)d_in[2];
    const float* Whh_f = (const float*)d_in[3];
    const float* b_f   = (const float*)d_in[4];
    const float* Wih_b = (const float*)d_in[5];
    const float* Whh_b = (const float*)d_in[6];
    const float* b_b   = (const float*)d_in[7];
    const float* Wl    = (const float*)d_in[8];
    const float* bl    = (const float*)d_in[9];
    const float* Wi1   = (const float*)d_in[10];
    const float* bi1   = (const float*)d_in[11];
    const float* Wi2   = (const float*)d_in[12];
    const float* bi2   = (const float*)d_in[13];
    const float* Wc1   = (const float*)d_in[14];
    const float* bc1   = (const float*)d_in[15];
    const float* Wc2   = (const float*)d_in[16];
    const float* bc2   = (const float*)d_in[17];
    const float* Wc3   = (const float*)d_in[18];
    const float* bc3   = (const float*)d_in[19];
    const float* Wc4   = (const float*)d_in[20];
    const float* bc4   = (const float*)d_in[21];
    float* out = (float*)d_out;

    float* hTm  = nullptr; cudaGetSymbolAddress((void**)&hTm,  g_hTm);
    float* bufA = nullptr; cudaGetSymbolAddress((void**)&bufA, g_bufAm);
    float* bufB = nullptr; cudaGetSymbolAddress((void**)&bufB, g_bufBm);
    float* zi2  = nullptr; cudaGetSymbolAddress((void**)&zi2,  g_zi2);

    static bool attr_done = false;
    if (!attr_done) {
        cudaFuncSetAttribute(lstm_kernel, cudaFuncAttributeMaxDynamicSharedMemorySize, 122880);
        attr_done = true;
    }

    // encoder
    pre_kernel<<<(SEQ * NCH) / 256, 256>>>(x_t, x_aug, Wih_f, b_f, Wih_b, b_b);
    lstm_kernel<<<1, 256, 122880>>>(Whh_f, Whh_b);
    combine_kernel<<<(SEQ * 32) / 256, 256>>>(Wl, bl);

    // instance head: 17520 -> 8760 -> 1752
    gemm_kernel<<<dim3(69, 9), 128>>>(hTm, Wi1, 8760, 17520);
    reduce_kernel<<<(8760 * 8 + 255) / 256, 256>>>(bi1, bufB, 8760, 69, 9);
    gemm_kernel<<<dim3(14, 42), 128>>>(bufB, Wi2, 1752, 8760);
    reduce_kernel<<<(1752 * 8 + 255) / 256, 256>>>(bi2, zi2, 1752, 14, 42);

    // cluster head: 17520 -> 13140 -> 8760 -> 4380 -> 10
    gemm_kernel<<<dim3(103, 6), 128>>>(hTm, Wc1, 13140, 17520);
    reduce_kernel<<<(13140 * 8 + 255) / 256, 256>>>(bc1, bufA, 13140, 103, 6);
    gemm_kernel<<<dim3(69, 9), 128>>>(bufA, Wc2, 8760, 13140);
    reduce_kernel<<<(8760 * 8 + 255) / 256, 256>>>(bc2, bufB, 8760, 69, 9);
    gemm_kernel<<<dim3(35, 17), 128>>>(bufB, Wc3, 4380, 8760);
    reduce_kernel<<<(4380 * 8 + 255) / 256, 256>>>(bc3, bufA, 4380, 35, 17);
    cluster4_kernel<<<10, 256>>>(Wc4, bc4);

    // epilogues
    norm_kernel<<<32, 256>>>(out);
    softmax_kernel<<<1, 32>>>(out);
}

// round 17
// speedup vs baseline: 1.2530x; 1.2530x over previous
#include <cuda_runtime.h>
#include <math.h>

#define SEQ 17520
#define NCH 64
#define CHUNK 48
#define N1CH 243          // part-1 chunks: 243*48 = 11664 exec steps
#define CH2 16
#define N2CH 366          // part-2: 366*16 = 5856; 11664+5856 = 17520
#define EX2OFF 11664
#define WC1_SLOT 828      // Wc1 partial region base (Wi1 owns 0..827)

typedef unsigned long long u64;

// ---------------- device scratch ----------------
__device__ float4 g_pre4[SEQ * NCH];
__device__ float  g_hraw[SEQ * NCH];
__device__ float  g_state[128];            // h[64], C[64] handoff
__device__ float  g_hT[SEQ * 32];          // [t][m]
__device__ float  g_bufA[13140 * 32];
__device__ float  g_bufB[8760 * 32];
__device__ float  g_zi2[1752 * 32];
__device__ float  g_zc4[10 * 32];
__device__ float  g_part[8454144];         // 2064 slots * 4096

// ---------------- helpers ----------------
__device__ __forceinline__ float tanhf_a(float x) {
    float y; asm("tanh.approx.f32 %0, %1;" : "=f"(y) : "f"(x)); return y;
}
__device__ __forceinline__ u64 ffma2(u64 a, u64 b, u64 c) {
    u64 d; asm("fma.rn.f32x2 %0, %1, %2, %3;" : "=l"(d) : "l"(a), "l"(b), "l"(c)); return d;
}
__device__ __forceinline__ u64 pack2(float x, float y) {
    u64 d; unsigned ux = __float_as_uint(x), uy = __float_as_uint(y);
    asm("mov.b64 %0, {%1, %2};" : "=l"(d) : "r"(ux), "r"(uy)); return d;
}
__device__ __forceinline__ u64 dup2(float x) {
    u64 d; unsigned ux = __float_as_uint(x);
    asm("mov.b64 %0, {%1, %1};" : "=l"(d) : "r"(ux)); return d;
}
__device__ __forceinline__ void cp16(void* dst_smem, const void* src_gmem, bool ok) {
    unsigned dst = (unsigned)__cvta_generic_to_shared(dst_smem);
    int sz = ok ? 16 : 0;
    asm volatile("cp.async.cg.shared.global [%0], [%1], 16, %2;"
                 :: "r"(dst), "l"(src_gmem), "r"(sz));
}
__device__ __forceinline__ void cp_commit() { asm volatile("cp.async.commit_group;"); }

// ---------------- 1. gate-affine precompute ----------------
__global__ void pre_kernel(const float* __restrict__ x_t, const float* __restrict__ x_aug,
                           const float* __restrict__ Wih_f, const float* __restrict__ b_f,
                           const float* __restrict__ Wih_b, const float* __restrict__ b_b) {
    int idx = blockIdx.x * 256 + threadIdx.x;
    int c = idx & 63, t = idx >> 6;
    int in = c >> 5, dir = (c >> 4) & 1, b = c & 15;
    const float* x   = in  ? x_aug : x_t;
    const float* Wih = dir ? Wih_b : Wih_f;
    const float* bb  = dir ? b_b   : b_f;
    float xv = x[b * SEQ + (dir ? (SEQ - 1 - t) : t)];
    float4 o;
    o.x = 0.5f * fmaf(xv, Wih[0], bb[0]);
    o.y = 0.5f * fmaf(xv, Wih[1], bb[1]);
    o.z =        fmaf(xv, Wih[2], bb[2]);
    o.w = 0.5f * fmaf(xv, Wih[3], bb[3]);
    g_pre4[t * NCH + c] = o;
}

// ---------------- LSTM step ----------------
__device__ __forceinline__ void lstm_step(float4 p, float& h, float& C,
                                          float wi2, float wf2, float wg, float wo2) {
    float ti = tanhf_a(fmaf(h, wi2, p.x));
    float tf = tanhf_a(fmaf(h, wf2, p.y));
    float tg = tanhf_a(fmaf(h, wg,  p.z));
    float to = tanhf_a(fmaf(h, wo2, p.w));
    float i = fmaf(ti, 0.5f, 0.5f);
    float f = fmaf(tf, 0.5f, 0.5f);
    float o = fmaf(to, 0.5f, 0.5f);
    C = fmaf(f, C, i * tg);
    h = o * tanhf_a(C);
}

// ---------------- 2a. LSTM part 1: chunks [0, 243) ----------------
extern __shared__ char dynsmem[];

__global__ void __launch_bounds__(256, 1)
lstm1_kernel(const float* __restrict__ Whh_f, const float* __restrict__ Whh_b) {
    float4* sbuf = (float4*)dynsmem;                               // [2][CHUNK*64]
    float*  sh   = (float*)(dynsmem + 2 * CHUNK * 64 * 16);        // [2][CHUNK*64]
    int tid = threadIdx.x;

    if (tid >= 64) {
        int pt = tid - 64;
        const float4* src = (const float4*)g_pre4;
        for (int i = pt; i < CHUNK * 64; i += 192) sbuf[i] = src[i];
    }
    __syncthreads();

    if (tid < 64) {
        int c = tid;
        int dir = (c >> 4) & 1;
        const float* Whh = dir ? Whh_b : Whh_f;
        float wi2 = 0.5f * Whh[0], wf2 = 0.5f * Whh[1];
        float wg  =        Whh[2], wo2 = 0.5f * Whh[3];
        float h = 0.0f, C = 0.0f;
        for (int ch = 0; ch < N1CH; ++ch) {
            int cur = ch & 1;
            const float4* buf = sbuf + cur * CHUNK * 64;
            float* hdst = sh + cur * CHUNK * 64;
            float4 p = buf[c];
#pragma unroll 4
            for (int s = 0; s < CHUNK; ++s) {
                float4 pn = buf[(s + 1) * 64 + c];
                lstm_step(p, h, C, wi2, wf2, wg, wo2);
                hdst[s * 64 + c] = h;
                p = pn;
            }
            __syncthreads();
        }
        g_state[c] = h; g_state[64 + c] = C;
    } else {
        int pt = tid - 64;
        const float4* src = (const float4*)g_pre4;
        for (int ch = 0; ch < N1CH; ++ch) {
            int cur = ch & 1, nxt = cur ^ 1;
            if (ch + 1 < N1CH) {
                const float4* s4 = src + (size_t)(ch + 1) * CHUNK * 64;
                float4* d4 = sbuf + nxt * CHUNK * 64;
                for (int i = pt; i < CHUNK * 64; i += 192) d4[i] = s4[i];
            }
            if (ch >= 1) {
                const float* hs = sh + nxt * CHUNK * 64;
                float* gd = g_hraw + (size_t)(ch - 1) * CHUNK * 64;
                for (int i = pt; i < CHUNK * 64; i += 192) gd[i] = hs[i];
            }
            __syncthreads();
        }
        const float* hs = sh + ((N1CH - 1) & 1) * CHUNK * 64;
        float* gd = g_hraw + (size_t)(N1CH - 1) * CHUNK * 64;
        for (int i = pt; i < CHUNK * 64; i += 192) gd[i] = hs[i];
    }
}

// ---------------- 2b. LSTM part 2 body (128 threads, CH2=16) ----------------
__device__ __forceinline__ void lstm2_body(char* sm, const float* __restrict__ Whh_f,
                                           const float* __restrict__ Whh_b) {
    float4* sbuf = (float4*)sm;                           // [2][CH2*64] = 32KB
    float*  sh   = (float*)(sm + 2 * CH2 * 64 * 16);      // [2][CH2*64] = 8KB
    int tid = threadIdx.x;

    if (tid >= 64) {
        int pt = tid - 64;
        const float4* src = g_pre4 + (size_t)EX2OFF * 64;
        for (int i = pt; i < CH2 * 64; i += 64) sbuf[i] = src[i];
    }
    __syncthreads();

    if (tid < 64) {
        int c = tid;
        int dir = (c >> 4) & 1;
        const float* Whh = dir ? Whh_b : Whh_f;
        float wi2 = 0.5f * Whh[0], wf2 = 0.5f * Whh[1];
        float wg  =        Whh[2], wo2 = 0.5f * Whh[3];
        float h = g_state[c], C = g_state[64 + c];
        for (int ch = 0; ch < N2CH; ++ch) {
            int cur = ch & 1;
            const float4* buf = sbuf + cur * CH2 * 64;
            float* hdst = sh + cur * CH2 * 64;
            float4 p = buf[c];
#pragma unroll 4
            for (int s = 0; s < CH2; ++s) {
                float4 pn = buf[(s + 1) * 64 + c];     // s=15 overread stays in-smem
                lstm_step(p, h, C, wi2, wf2, wg, wo2);
                hdst[s * 64 + c] = h;
                p = pn;
            }
            __syncthreads();
        }
    } else {
        int pt = tid - 64;
        for (int ch = 0; ch < N2CH; ++ch) {
            int cur = ch & 1, nxt = cur ^ 1;
            if (ch + 1 < N2CH) {
                const float4* s4 = g_pre4 + (size_t)(EX2OFF + (ch + 1) * CH2) * 64;
                float4* d4 = sbuf + nxt * CH2 * 64;
                for (int i = pt; i < CH2 * 64; i += 64) d4[i] = s4[i];
            }
            if (ch >= 1) {
                const float* hs = sh + nxt * CH2 * 64;
                float* gd = g_hraw + (size_t)(EX2OFF + (ch - 1) * CH2) * 64;
                for (int i = pt; i < CH2 * 64; i += 64) gd[i] = hs[i];
            }
            __syncthreads();
        }
        const float* hs = sh + ((N2CH - 1) & 1) * CH2 * 64;
        float* gd = g_hraw + (size_t)(EX2OFF + (N2CH - 1) * CH2) * 64;
        for (int i = pt; i < CH2 * 64; i += 64) gd[i] = hs[i];
    }
}

// ---------------- 3. combine (t range) -> g_hT [t][m] ----------------
__global__ void combine_kernel(const float* __restrict__ Wl, const float* __restrict__ bl,
                               int t_off) {
    int idx = blockIdx.x * 256 + threadIdx.x;
    int t = t_off + (idx >> 5), m = idx & 31;
    int in = m >> 4, b = m & 15;
    float hf = g_hraw[(size_t)t * 64 + in * 32 + b];
    float hb = g_hraw[(size_t)(SEQ - 1 - t) * 64 + in * 32 + 16 + b];
    g_hT[(size_t)t * 32 + m] = fmaf(Wl[0], hf, fmaf(Wl[1], hb, bl[0]));
}

// ---------------- 4. GEMM core (R11 inner loop) ----------------
struct GSmem {
    float sW[2][128][36];    // 36864 B
    float sA[2][32][32];     // 8192 B
};

__device__ __forceinline__ void gemm_core(GSmem& S, const float* __restrict__ A,
                                          const float* __restrict__ W, int N, int ldW,
                                          int n0, int k0, int k1, size_t slot) {
    int t = threadIdx.x;
    int tg = t >> 3, m0 = (t & 7) * 4;
    int nt = (k1 - k0 + 31) / 32;

    u64 acc[8][2];
#pragma unroll
    for (int j = 0; j < 8; ++j) { acc[j][0] = 0ULL; acc[j][1] = 0ULL; }

    auto issue = [&](int b, int kb) {
#pragma unroll
        for (int r = 0; r < 8; ++r) {
            int n = n0 + tg + 16 * r;
            int kq = kb + m0;
            bool ok = (n < N) && (kq < k1);
            const float* src = ok ? (W + (size_t)n * ldW + kq) : W;
            cp16(&S.sW[b][tg + 16 * r][m0], src, ok);
        }
#pragma unroll
        for (int r = 0; r < 2; ++r) {
            int k = kb + tg + 16 * r;
            bool ok = (k < k1);
            const float* src = ok ? (A + (size_t)k * 32 + m0) : A;
            cp16(&S.sA[b][tg + 16 * r][m0], src, ok);
        }
        cp_commit();
    };

    issue(0, k0);
    for (int it = 0; it < nt; ++it) {
        int buf = it & 1;
        if (it + 1 < nt) {
            issue(buf ^ 1, k0 + (it + 1) * 32);
            asm volatile("cp.async.wait_group 1;");
        } else {
            asm volatile("cp.async.wait_group 0;");
        }
        __syncthreads();
#pragma unroll
        for (int k4 = 0; k4 < 8; ++k4) {
            float4 a0 = *(const float4*)&S.sA[buf][4 * k4 + 0][m0];
            float4 a1 = *(const float4*)&S.sA[buf][4 * k4 + 1][m0];
            float4 a2 = *(const float4*)&S.sA[buf][4 * k4 + 2][m0];
            float4 a3 = *(const float4*)&S.sA[buf][4 * k4 + 3][m0];
            u64 a0l = pack2(a0.x, a0.y), a0h = pack2(a0.z, a0.w);
            u64 a1l = pack2(a1.x, a1.y), a1h = pack2(a1.z, a1.w);
            u64 a2l = pack2(a2.x, a2.y), a2h = pack2(a2.z, a2.w);
            u64 a3l = pack2(a3.x, a3.y), a3h = pack2(a3.z, a3.w);
#pragma unroll
            for (int j = 0; j < 8; ++j) {
                float4 w = *(const float4*)&S.sW[buf][tg + 16 * j][4 * k4];
                u64 wx = dup2(w.x), wy = dup2(w.y), wz = dup2(w.z), ww = dup2(w.w);
                acc[j][0] = ffma2(wx, a0l, acc[j][0]); acc[j][1] = ffma2(wx, a0h, acc[j][1]);
                acc[j][0] = ffma2(wy, a1l, acc[j][0]); acc[j][1] = ffma2(wy, a1h, acc[j][1]);
                acc[j][0] = ffma2(wz, a2l, acc[j][0]); acc[j][1] = ffma2(wz, a2h, acc[j][1]);
                acc[j][0] = ffma2(ww, a3l, acc[j][0]); acc[j][1] = ffma2(ww, a3h, acc[j][1]);
            }
        }
        __syncthreads();
    }
    size_t base = slot * 4096;
#pragma unroll
    for (int j = 0; j < 8; ++j) {
        size_t idx = base + (size_t)(tg + 16 * j) * 32 + m0;
        *(u64*)&g_part[idx]     = acc[j][0];
        *(u64*)&g_part[idx + 2] = acc[j][1];
    }
}

// single-range standalone GEMM; slot = slot_off + bs*ntiles + bt
__global__ void __launch_bounds__(128, 5)
gemm_kernel(const float* __restrict__ A, const float* __restrict__ W,
            int N, int ldW, int koff, int klen, int slot_off) {
    __shared__ __align__(16) GSmem S;
    int bt = blockIdx.x, bs = blockIdx.y, nsp = gridDim.y, ntiles = gridDim.x;
    int k0 = koff + ((int)(((long long)klen * bs) / nsp) & ~3);
    int k1 = (bs == nsp - 1) ? (koff + klen)
                             : (koff + ((int)(((long long)klen * (bs + 1)) / nsp) & ~3));
    size_t slot = (size_t)slot_off + (size_t)bs * ntiles + bt;
    gemm_core(S, A, W, N, ldW, bt * 128, k0, k1, slot);
}

// dual-range standalone GEMM (lo+hi k-ends in one launch)
__global__ void __launch_bounds__(128, 5)
gemm2_kernel(const float* __restrict__ A, const float* __restrict__ W,
             int N, int ldW, int koffA, int klenA, int nspA,
             int koffB, int klenB, int slot_off) {
    __shared__ __align__(16) GSmem S;
    int bt = blockIdx.x, bs = blockIdx.y, ntiles = gridDim.x;
    int koff, klen, bsl, nsp;
    if (bs < nspA) { koff = koffA; klen = klenA; bsl = bs; nsp = nspA; }
    else { koff = koffB; klen = klenB; bsl = bs - nspA; nsp = gridDim.y - nspA; }
    int k0 = koff + ((int)(((long long)klen * bsl) / nsp) & ~3);
    int k1 = (bsl == nsp - 1) ? (koff + klen)
                              : (koff + ((int)(((long long)klen * (bsl + 1)) / nsp) & ~3));
    size_t slot = (size_t)slot_off + (size_t)bs * ntiles + bt;
    gemm_core(S, A, W, N, ldW, bt * 128, k0, k1, slot);
}

// ---------------- fused: block0 = LSTM part2; others = Wi1/Wc1 mid-k GEMM --------
__global__ void __launch_bounds__(128, 5)
fused_kernel(const float* __restrict__ Whh_f, const float* __restrict__ Whh_b,
             const float* __restrict__ hT,
             const float* __restrict__ Wi1, const float* __restrict__ Wc1) {
    __shared__ __align__(16) char sm[sizeof(GSmem)];
    int bx = blockIdx.x;
    if (bx == 0) {
        lstm2_body(sm, Whh_f, Whh_b);
    } else if (bx <= 276) {                      // Wi1 mid: 69 tiles x 4 splits -> slots 0..275
        int b = bx - 1, bt = b % 69, bs = b / 69;
        int k0 = 5888 + bs * 1440, k1 = k0 + 1440;
        gemm_core(*(GSmem*)sm, hT, Wi1, 8760, 17520, bt * 128, k0, k1,
                  (size_t)bs * 69 + bt);
    } else {                                     // Wc1 mid: slots WC1_SLOT..WC1_SLOT+411
        int b = bx - 277, bt = b % 103, bs = b / 103;
        int k0 = 5888 + bs * 1440, k1 = k0 + 1440;
        gemm_core(*(GSmem*)sm, hT, Wc1, 13140, 17520, bt * 128, k0, k1,
                  (size_t)WC1_SLOT + (size_t)bs * 103 + bt);
    }
}

// ---------------- 5. split-K reduce + bias -> out [n][32] ----------------
__global__ void reduce_kernel(const float* __restrict__ bias, float* __restrict__ out,
                              int N, int ntiles, int nsplit, int slot_off) {
    int q = blockIdx.x * 256 + threadIdx.x;
    if (q >= N * 8) return;
    int n = q >> 3, m4 = (q & 7) * 4;
    int bt = n >> 7, nl = n & 127;
    float b = bias[n];
    float4 s = make_float4(b, b, b, b);
    for (int sp = 0; sp < nsplit; ++sp) {
        size_t slot = (size_t)slot_off + (size_t)sp * ntiles + bt;
        const float4 v = *(const float4*)&g_part[(slot * 128 + nl) * 32 + m4];
        s.x += v.x; s.y += v.y; s.z += v.z; s.w += v.w;
    }
    *(float4*)&out[(size_t)n * 32 + m4] = s;
}

// ---------------- 6. tiny final cluster GEMM (10 x 4380) ----------------
__global__ void cluster4_kernel(const float* __restrict__ W, const float* __restrict__ bias) {
    __shared__ float red[8][32];
    int n = blockIdx.x, t = threadIdx.x;
    int m = t & 31, seg = t >> 5;
    float s = 0.0f;
    for (int k = seg; k < 4380; k += 8)
        s += g_bufA[k * 32 + m] * W[n * 4380 + k];
    red[seg][m] = s;
    __syncthreads();
    if (seg == 0) {
        float tot = bias[n];
#pragma unroll
        for (int j = 0; j < 8; ++j) tot += red[j][m];
        g_zc4[n * 32 + m] = tot;
    }
}

// ---------------- 7. instance-head L2 normalize -> d_out ----------------
__global__ void norm_kernel(float* __restrict__ out) {
    __shared__ float red[256];
    int m = blockIdx.x;
    float ss = 0.0f;
    for (int f = threadIdx.x; f < 1752; f += 256) {
        float v = g_zi2[f * 32 + m]; ss += v * v;
    }
    red[threadIdx.x] = ss; __syncthreads();
    for (int s = 128; s > 0; s >>= 1) {
        if (threadIdx.x < s) red[threadIdx.x] += red[threadIdx.x + s];
        __syncthreads();
    }
    float inv = 1.0f / fmaxf(sqrtf(red[0]), 1e-12f);
    int in = m >> 4, b = m & 15;
    float* dst = out + in * (16 * 1752) + b * 1752;
    for (int f = threadIdx.x; f < 1752; f += 256)
        dst[f] = g_zi2[f * 32 + m] * inv;
}

// ---------------- 8. cluster-head softmax -> d_out ----------------
__global__ void softmax_kernel(float* __restrict__ out) {
    int m = threadIdx.x;
    float v[10]; float mx = -1e30f;
#pragma unroll
    for (int c = 0; c < 10; ++c) { v[c] = g_zc4[c * 32 + m]; mx = fmaxf(mx, v[c]); }
    float sum = 0.0f;
#pragma unroll
    for (int c = 0; c < 10; ++c) { v[c] = __expf(v[c] - mx); sum += v[c]; }
    float inv = 1.0f / sum;
    int in = m >> 4, b = m & 15;
    float* dst = out + 2 * 16 * 1752 + in * 160 + b * 10;
#pragma unroll
    for (int c = 0; c < 10; ++c) dst[c] = v[c] * inv;
}

// ---------------- launch ----------------
extern "C" void kernel_launch(void* const* d_in, const int* in_sizes, int n_in,
                              void* d_out, int out_size) {
    const float* x_t   = (const float*)d_in[0];
    const float* x_aug = (const float*)d_in[1];
    const float* Wih_f = (const float*)d_in[2];
    const float* Whh_f = (const float*)d_in[3];
    const float* b_f   = (const float*)d_in[4];
    const float* Wih_b = (const float*)d_in[5];
    const float* Whh_b = (const float*)d_in[6];
    const float* b_b   = (const float*)d_in[7];
    const float* Wl    = (const float*)d_in[8];
    const float* bl    = (const float*)d_in[9];
    const float* Wi1   = (const float*)d_in[10];
    const float* bi1   = (const float*)d_in[11];
    const float* Wi2   = (const float*)d_in[12];
    const float* bi2   = (const float*)d_in[13];
    const float* Wc1   = (const float*)d_in[14];
    const float* bc1   = (const float*)d_in[15];
    const float* Wc2   = (const float*)d_in[16];
    const float* bc2   = (const float*)d_in[17];
    const float* Wc3   = (const float*)d_in[18];
    const float* bc3   = (const float*)d_in[19];
    const float* Wc4   = (const float*)d_in[20];
    const float* bc4   = (const float*)d_in[21];
    float* out = (float*)d_out;

    float* hT   = nullptr; cudaGetSymbolAddress((void**)&hT,   g_hT);
    float* bufA = nullptr; cudaGetSymbolAddress((void**)&bufA, g_bufA);
    float* bufB = nullptr; cudaGetSymbolAddress((void**)&bufB, g_bufB);
    float* zi2  = nullptr; cudaGetSymbolAddress((void**)&zi2,  g_zi2);

    static bool attr_done = false;
    if (!attr_done) {
        cudaFuncSetAttribute(lstm1_kernel, cudaFuncAttributeMaxDynamicSharedMemorySize, 122880);
        attr_done = true;
    }

    // encoder part 1: exec steps [0, 11664)
    pre_kernel<<<(SEQ * NCH) / 256, 256>>>(x_t, x_aug, Wih_f, b_f, Wih_b, b_b);
    lstm1_kernel<<<1, 256, 122880>>>(Whh_f, Whh_b);

    // middle t-range now fully determined
    combine_kernel<<<720, 256>>>(Wl, bl, 5888);          // t in [5888, 11648)

    // fused: LSTM part 2 (block 0) + Wi1/Wc1 mid-k GEMM (blocks 1..688)
    fused_kernel<<<689, 128>>>(Whh_f, Whh_b, hT, Wi1, Wc1);

    // combine remaining t ranges
    combine_kernel<<<736, 256>>>(Wl, bl, 0);             // t in [0, 5888)
    combine_kernel<<<734, 256>>>(Wl, bl, 11648);         // t in [11648, 17520)

    // Wi1/Wc1 over remaining k ranges (slots after the 4 fused splits)
    gemm2_kernel<<<dim3(69, 8), 128>>>(hT, Wi1, 8760, 17520, 0, 5888, 4, 11648, 5872,
                                       4 * 69);
    gemm2_kernel<<<dim3(103, 8), 128>>>(hT, Wc1, 13140, 17520, 0, 5888, 4, 11648, 5872,
                                        WC1_SLOT + 4 * 103);

    // instance head
    reduce_kernel<<<(8760 * 8 + 255) / 256, 256>>>(bi1, bufB, 8760, 69, 12, 0);
    gemm_kernel<<<dim3(14, 53), 128>>>(bufB, Wi2, 1752, 8760, 0, 8760, 0);
    reduce_kernel<<<(1752 * 8 + 255) / 256, 256>>>(bi2, zi2, 1752, 14, 53, 0);

    // cluster head
    reduce_kernel<<<(13140 * 8 + 255) / 256, 256>>>(bc1, bufA, 13140, 103, 12, WC1_SLOT);
    gemm_kernel<<<dim3(69, 11), 128>>>(bufA, Wc2, 8760, 13140, 0, 13140, 0);
    reduce_kernel<<<(8760 * 8 + 255) / 256, 256>>>(bc2, bufB, 8760, 69, 11, 0);
    gemm_kernel<<<dim3(35, 21), 128>>>(bufB, Wc3, 4380, 8760, 0, 8760, 0);
    reduce_kernel<<<(4380 * 8 + 255) / 256, 256>>>(bc3, bufA, 4380, 35, 21, 0);
    cluster4_kernel<<<10, 256>>>(Wc4, bc4);

    // epilogues
    norm_kernel<<<32, 256>>>(out);
    softmax_kernel<<<1, 32>>>(out);
}